// round 10
// baseline (speedup 1.0000x reference)
#include <cuda_runtime.h>
#include <cstdint>

#define HW     4096
#define CCH    256
#define BATCH  32
#define PROJ   50
#define NHEAD  5
#define LDIM   10
#define MROWS  (BATCH * CCH)       // 8192
#define FEAT   (CCH * LDIM)        // 2560
#define NSTAT  (BATCH * HW)

// ---------------- scratch ----------------------------------------------------
__device__ float g_P[3 * MROWS * PROJ];
__device__ float g_A[MROWS * PROJ];
__device__ float g_csum[CCH];
__device__ float g_csum2[CCH];

// hi = truncate-to-bf16 (top 16 bits); pack two hi's with one PRMT
__device__ __forceinline__ uint32_t pack_hi(float a, float b) {
    return __byte_perm(__float_as_uint(a), __float_as_uint(b), 0x7632);
}
__device__ __forceinline__ float trunc_bf(float a) {
    return __uint_as_float(__float_as_uint(a) & 0xFFFF0000u);
}
// pack two fp32 into bf16x2 with rne (used for the lo parts)
__device__ __forceinline__ uint32_t pack_bf16(float lo, float hi) {
    uint32_t d;
    asm("cvt.rn.bf16x2.f32 %0, %1, %2;" : "=r"(d) : "f"(hi), "f"(lo));
    return d;
}

__device__ __forceinline__ void mma_bf16(float* d, const uint32_t* a, const uint32_t* b) {
    asm volatile(
        "mma.sync.aligned.m16n8k16.row.col.f32.bf16.bf16.f32 "
        "{%0,%1,%2,%3}, {%4,%5,%6,%7}, {%8,%9}, {%0,%1,%2,%3};"
        : "+f"(d[0]), "+f"(d[1]), "+f"(d[2]), "+f"(d[3])
        : "r"(a[0]), "r"(a[1]), "r"(a[2]), "r"(a[3]), "r"(b[0]), "r"(b[1]));
}

// =====================================================================
// K1: projection GEMM, bf16 HMMA with 3-term hi/lo split (~fp32 accuracy).
// C[8192,50] = A[8192,4096] @ W[4096,50].  BM=128, BN=64(pad), BK=64.
// smem (dynamic 96KB): AsH/AsL [2][8][128][4] words, BsH/BsL [2][8][64][4].
// k = p4*8 + pj*2 (+0/1 inside the bf16x2 word). Fragment LDS conflict-free.
// 8 warps: 4 in m x 2 in n. Register prefetch 2 iters ahead (8 LDG.128/thr).
// =====================================================================
__global__ __launch_bounds__(256, 2) void proj_tc(
    const float* __restrict__ q, const float* __restrict__ k,
    const float* __restrict__ v,
    const float* __restrict__ wq, const float* __restrict__ wk,
    const float* __restrict__ wv)
{
    extern __shared__ uint32_t sm[];
    uint32_t* AsH = sm;            // 8192 words
    uint32_t* AsL = sm + 8192;
    uint32_t* BsH = sm + 16384;    // 4096 words
    uint32_t* BsL = sm + 20480;

#define AIDX(ST, P4, M, PJ) ((((ST) * 8 + (P4)) * 128 + (M)) * 4 + (PJ))
#define BIDX(ST, P4, N, PJ) ((((ST) * 8 + (P4)) * 64 + (N)) * 4 + (PJ))

    const int t = blockIdx.y;
    const float* A = (t == 0) ? q : (t == 1) ? k : v;
    const float* W = (t == 0) ? wq : (t == 1) ? wk : wv;
    float* C = g_P + (size_t)t * MROWS * PROJ;

    const int tid  = threadIdx.x;
    const int lane = tid & 31;
    const int warp = tid >> 5;
    const int wm   = warp & 3;
    const int wn   = warp >> 2;
    const int g    = lane >> 2;
    const int tt   = lane & 3;
    const int rowBase = blockIdx.x * 128;

    const int ma   = tid >> 1;       // A loader row
    const int half = tid & 1;        // A loader k-half (0..31 / 32..63)
    const int nb   = tid & 63;       // B loader n
    const int wsel = tid >> 6;       // B loader k-16-group

    const float* aPtr = A + (size_t)(rowBase + ma) * HW + half * 32;

    float4 pa[8];
    float  pb[16];
    float  acc[2][4][4];
#pragma unroll
    for (int mt = 0; mt < 2; mt++)
#pragma unroll
        for (int nt = 0; nt < 4; nt++)
#pragma unroll
            for (int r = 0; r < 4; r++) acc[mt][nt][r] = 0.f;

#define LOAD_REGS(K0)                                                         \
    do {                                                                      \
        _Pragma("unroll")                                                     \
        for (int s4 = 0; s4 < 8; s4++)                                        \
            pa[s4] = *(const float4*)&aPtr[(K0) + s4 * 4];                    \
        _Pragma("unroll")                                                     \
        for (int j = 0; j < 16; j++) {                                        \
            int kk = (K0) + wsel * 16 + j;                                    \
            pb[j] = (nb < PROJ) ? W[(size_t)kk * PROJ + nb] : 0.f;            \
        }                                                                     \
    } while (0)

#define STORE_SMEM(ST)                                                        \
    do {                                                                      \
        _Pragma("unroll")                                                     \
        for (int s4 = 0; s4 < 8; s4++) {                                      \
            int p4 = half * 4 + (s4 >> 1);                                    \
            int pj = (s4 & 1) * 2;                                            \
            uint2 uh, ul;                                                     \
            uh.x = pack_hi(pa[s4].x, pa[s4].y);                               \
            uh.y = pack_hi(pa[s4].z, pa[s4].w);                               \
            ul.x = pack_bf16(pa[s4].x - trunc_bf(pa[s4].x),                   \
                             pa[s4].y - trunc_bf(pa[s4].y));                  \
            ul.y = pack_bf16(pa[s4].z - trunc_bf(pa[s4].z),                   \
                             pa[s4].w - trunc_bf(pa[s4].w));                  \
            *(uint2*)&AsH[AIDX(ST, p4, ma, pj)] = uh;                         \
            *(uint2*)&AsL[AIDX(ST, p4, ma, pj)] = ul;                         \
        }                                                                     \
        _Pragma("unroll")                                                     \
        for (int jj = 0; jj < 8; jj++) {                                      \
            int p4 = wsel * 2 + (jj >> 2);                                    \
            int pj = jj & 3;                                                  \
            float f0 = pb[2 * jj], f1 = pb[2 * jj + 1];                       \
            BsH[BIDX(ST, p4, nb, pj)] = pack_hi(f0, f1);                      \
            BsL[BIDX(ST, p4, nb, pj)] =                                       \
                pack_bf16(f0 - trunc_bf(f0), f1 - trunc_bf(f1));              \
        }                                                                     \
    } while (0)

    // prologue
    LOAD_REGS(0);
    STORE_SMEM(0);
    LOAD_REGS(64);
    __syncthreads();

    const int NIT = HW / 64;
    for (int it = 0; it < NIT; it++) {
        const int st = it & 1;
        if (it + 1 < NIT) STORE_SMEM(st ^ 1);
        if (it + 2 < NIT) LOAD_REGS((it + 2) * 64);

        // compute stage st: four k16 steps, 3 MMA terms each
#pragma unroll
        for (int ck = 0; ck < 4; ck++) {
            uint32_t ah[2][4], al[2][4], bh[4][2], bl[4][2];
#pragma unroll
            for (int mt = 0; mt < 2; mt++) {
                int mo = wm * 32 + mt * 16;
                int i0 = AIDX(st, ck * 2, mo + g, tt);
                int i1 = AIDX(st, ck * 2, mo + 8 + g, tt);
                int i2 = AIDX(st, ck * 2 + 1, mo + g, tt);
                int i3 = AIDX(st, ck * 2 + 1, mo + 8 + g, tt);
                ah[mt][0] = AsH[i0]; ah[mt][1] = AsH[i1];
                ah[mt][2] = AsH[i2]; ah[mt][3] = AsH[i3];
                al[mt][0] = AsL[i0]; al[mt][1] = AsL[i1];
                al[mt][2] = AsL[i2]; al[mt][3] = AsL[i3];
            }
#pragma unroll
            for (int nt = 0; nt < 4; nt++) {
                int no = wn * 32 + nt * 8;
                int i0 = BIDX(st, ck * 2, no + g, tt);
                int i1 = BIDX(st, ck * 2 + 1, no + g, tt);
                bh[nt][0] = BsH[i0]; bh[nt][1] = BsH[i1];
                bl[nt][0] = BsL[i0]; bl[nt][1] = BsL[i1];
            }
#pragma unroll
            for (int mt = 0; mt < 2; mt++)
#pragma unroll
                for (int nt = 0; nt < 4; nt++) {
                    mma_bf16(acc[mt][nt], ah[mt], bh[nt]);
                    mma_bf16(acc[mt][nt], ah[mt], bl[nt]);
                    mma_bf16(acc[mt][nt], al[mt], bh[nt]);
                }
        }
        __syncthreads();
    }
#undef LOAD_REGS
#undef STORE_SMEM

    // epilogue
#pragma unroll
    for (int mt = 0; mt < 2; mt++) {
        int r0 = rowBase + wm * 32 + mt * 16 + g;
#pragma unroll
        for (int nt = 0; nt < 4; nt++) {
            int c0 = wn * 32 + nt * 8 + tt * 2;
            if (c0 < PROJ) {
                *(float2*)&C[(size_t)r0 * PROJ + c0] =
                    make_float2(acc[mt][nt][0], acc[mt][nt][1]);
                *(float2*)&C[(size_t)(r0 + 8) * PROJ + c0] =
                    make_float2(acc[mt][nt][2], acc[mt][nt][3]);
            }
        }
    }
}

// =====================================================================
// K2: tiny attention per batch. Also zeroes BN accumulators.
// =====================================================================
__global__ __launch_bounds__(256) void attn_kernel()
{
    __shared__ float sS[NHEAD * NHEAD];
    __shared__ float sAttn[NHEAD * NHEAD];

    const int b = blockIdx.x;
    const int c = threadIdx.x;
    const int lane = threadIdx.x & 31;

    if (blockIdx.x == 0) { g_csum[c] = 0.f; g_csum2[c] = 0.f; }
    if (c < NHEAD * NHEAD) sS[c] = 0.f;
    __syncthreads();

    const size_t rowOff = (size_t)(b * CCH + c) * PROJ;
    const float* Pq = g_P + rowOff;
    const float* Pk = g_P + (size_t)MROWS * PROJ + rowOff;
    const float* Pv = g_P + 2 * (size_t)MROWS * PROJ + rowOff;

    float qv[PROJ], kv[PROJ];
#pragma unroll
    for (int x = 0; x < PROJ / 2; x++) {
        float2 a = *(const float2*)&Pq[x * 2];
        float2 bq = *(const float2*)&Pk[x * 2];
        qv[x * 2] = a.x; qv[x * 2 + 1] = a.y;
        kv[x * 2] = bq.x; kv[x * 2 + 1] = bq.y;
    }

#pragma unroll
    for (int i = 0; i < NHEAD; i++) {
#pragma unroll
        for (int j = 0; j < NHEAD; j++) {
            float s = 0.f;
#pragma unroll
            for (int l = 0; l < LDIM; l++) s += qv[i * LDIM + l] * kv[j * LDIM + l];
#pragma unroll
            for (int off = 16; off; off >>= 1)
                s += __shfl_down_sync(0xffffffffu, s, off);
            if (lane == 0) atomicAdd(&sS[i * NHEAD + j], s);
        }
    }
    __syncthreads();

    if (c < NHEAD) {
        const float inv_scale = rsqrtf((float)FEAT);
        float row[NHEAD];
        float mx = -1e30f;
#pragma unroll
        for (int j = 0; j < NHEAD; j++) {
            row[j] = sS[c * NHEAD + j] * inv_scale;
            mx = fmaxf(mx, row[j]);
        }
        float sum = 0.f;
#pragma unroll
        for (int j = 0; j < NHEAD; j++) { row[j] = __expf(row[j] - mx); sum += row[j]; }
        float rinv = 1.f / sum;
#pragma unroll
        for (int j = 0; j < NHEAD; j++) sAttn[c * NHEAD + j] = row[j] * rinv;
    }
    __syncthreads();

    float v50[PROJ];
#pragma unroll
    for (int x = 0; x < PROJ / 2; x++) {
        float2 a = *(const float2*)&Pv[x * 2];
        v50[x * 2] = a.x; v50[x * 2 + 1] = a.y;
    }

    float* Aout = g_A + rowOff;
#pragma unroll
    for (int i = 0; i < NHEAD; i++) {
#pragma unroll
        for (int l = 0; l < LDIM; l += 2) {
            float a0 = v50[i * LDIM + l], a1 = v50[i * LDIM + l + 1];
#pragma unroll
            for (int j = 0; j < NHEAD; j++) {
                float w = sAttn[i * NHEAD + j];
                a0 += w * v50[j * LDIM + l];
                a1 += w * v50[j * LDIM + l + 1];
            }
            *(float2*)&Aout[i * LDIM + l] = make_float2(a0, a1);
        }
    }
}

// =====================================================================
// K3: FC GEMM (bf16 HMMA, 3-term hi/lo) + residual + BN partial stats.
// out[m,n] = vf[m,n] + A[m,:50] @ Wfc[:50,n].  BM=128, BN=64, K pad 64.
// smem dynamic 48KB: AsH/AsL [8][128][4], BsH/BsL [8][64][4].
// =====================================================================
__global__ __launch_bounds__(256) void fc_tc(
    const float* __restrict__ vf, const float* __restrict__ wfc,
    float* __restrict__ out)
{
    extern __shared__ uint32_t sm[];
    uint32_t* AsH = sm;            // 4096 words
    uint32_t* AsL = sm + 4096;
    uint32_t* BsH = sm + 8192;     // 2048 words
    uint32_t* BsL = sm + 10240;

    const int tid  = threadIdx.x;
    const int lane = tid & 31;
    const int warp = tid >> 5;
    const int wm   = warp & 3;
    const int wn   = warp >> 2;
    const int g    = lane >> 2;
    const int tt   = lane & 3;
    const int rowBase = blockIdx.y * 128;
    const int colBase = blockIdx.x * 64;

    // A tile: 4096 words, widx = p4*512 + m*4 + pj
#pragma unroll
    for (int ii = 0; ii < 16; ii++) {
        int widx = ii * 256 + tid;
        int p4 = widx >> 9;
        int m  = (widx >> 2) & 127;
        int pj = widx & 3;
        int kk = p4 * 8 + pj * 2;
        const float* src = &g_A[(size_t)(rowBase + m) * PROJ + kk];
        float v0 = (kk < PROJ) ? src[0] : 0.f;
        float v1 = (kk + 1 < PROJ) ? src[1] : 0.f;
        AsH[widx] = pack_hi(v0, v1);
        AsL[widx] = pack_bf16(v0 - trunc_bf(v0), v1 - trunc_bf(v1));
    }
    // B tile: 2048 words, widx = p4*256 + n*4 + pj
#pragma unroll
    for (int ii = 0; ii < 8; ii++) {
        int widx = ii * 256 + tid;
        int p4 = widx >> 8;
        int n  = (widx >> 2) & 63;
        int pj = widx & 3;
        int kk = p4 * 8 + pj * 2;
        float v0 = (kk < PROJ) ? wfc[(size_t)kk * HW + colBase + n] : 0.f;
        float v1 = (kk + 1 < PROJ) ? wfc[(size_t)(kk + 1) * HW + colBase + n] : 0.f;
        BsH[widx] = pack_hi(v0, v1);
        BsL[widx] = pack_bf16(v0 - trunc_bf(v0), v1 - trunc_bf(v1));
    }
    __syncthreads();

    float acc[2][4][4];
#pragma unroll
    for (int mt = 0; mt < 2; mt++)
#pragma unroll
        for (int nt = 0; nt < 4; nt++)
#pragma unroll
            for (int r = 0; r < 4; r++) acc[mt][nt][r] = 0.f;

#pragma unroll
    for (int ck = 0; ck < 4; ck++) {
        uint32_t ah[2][4], al[2][4], bh[4][2], bl[4][2];
#pragma unroll
        for (int mt = 0; mt < 2; mt++) {
            int mo = wm * 32 + mt * 16;
            int i0 = (ck * 2) * 512 + (mo + g) * 4 + tt;
            int i1 = (ck * 2) * 512 + (mo + 8 + g) * 4 + tt;
            int i2 = (ck * 2 + 1) * 512 + (mo + g) * 4 + tt;
            int i3 = (ck * 2 + 1) * 512 + (mo + 8 + g) * 4 + tt;
            ah[mt][0] = AsH[i0]; ah[mt][1] = AsH[i1];
            ah[mt][2] = AsH[i2]; ah[mt][3] = AsH[i3];
            al[mt][0] = AsL[i0]; al[mt][1] = AsL[i1];
            al[mt][2] = AsL[i2]; al[mt][3] = AsL[i3];
        }
#pragma unroll
        for (int nt = 0; nt < 4; nt++) {
            int no = wn * 32 + nt * 8;
            int i0 = (ck * 2) * 256 + (no + g) * 4 + tt;
            int i1 = (ck * 2 + 1) * 256 + (no + g) * 4 + tt;
            bh[nt][0] = BsH[i0]; bh[nt][1] = BsH[i1];
            bl[nt][0] = BsL[i0]; bl[nt][1] = BsL[i1];
        }
#pragma unroll
        for (int mt = 0; mt < 2; mt++)
#pragma unroll
            for (int nt = 0; nt < 4; nt++) {
                mma_bf16(acc[mt][nt], ah[mt], bh[nt]);
                mma_bf16(acc[mt][nt], ah[mt], bl[nt]);
                mma_bf16(acc[mt][nt], al[mt], bh[nt]);
            }
    }

#pragma unroll
    for (int mt = 0; mt < 2; mt++) {
        int r0 = rowBase + wm * 32 + mt * 16 + g;
        int r1 = r0 + 8;
        float s0 = 0.f, q0 = 0.f, s1 = 0.f, q1 = 0.f;
#pragma unroll
        for (int nt = 0; nt < 4; nt++) {
            int c0 = colBase + wn * 32 + nt * 8 + tt * 2;
            size_t i00 = (size_t)r0 * HW + c0;
            size_t i10 = (size_t)r1 * HW + c0;
            float2 rv0 = *(const float2*)&vf[i00];
            float2 rv1 = *(const float2*)&vf[i10];
            float v00 = acc[mt][nt][0] + rv0.x;
            float v01 = acc[mt][nt][1] + rv0.y;
            float v10 = acc[mt][nt][2] + rv1.x;
            float v11 = acc[mt][nt][3] + rv1.y;
            *(float2*)&out[i00] = make_float2(v00, v01);
            *(float2*)&out[i10] = make_float2(v10, v11);
            s0 += v00 + v01; q0 += v00 * v00 + v01 * v01;
            s1 += v10 + v11; q1 += v10 * v10 + v11 * v11;
        }
#pragma unroll
        for (int off = 1; off < 4; off <<= 1) {
            s0 += __shfl_xor_sync(0xffffffffu, s0, off);
            q0 += __shfl_xor_sync(0xffffffffu, q0, off);
            s1 += __shfl_xor_sync(0xffffffffu, s1, off);
            q1 += __shfl_xor_sync(0xffffffffu, q1, off);
        }
        if (tt == 0) {
            atomicAdd(&g_csum[r0 & (CCH - 1)],  s0);
            atomicAdd(&g_csum2[r0 & (CCH - 1)], q0);
            atomicAdd(&g_csum[r1 & (CCH - 1)],  s1);
            atomicAdd(&g_csum2[r1 & (CCH - 1)], q1);
        }
    }
}

// =====================================================================
// K4: BatchNorm finalize, in-place. float4 per thread.
// =====================================================================
__global__ __launch_bounds__(256) void bn_kernel(
    float* __restrict__ out, const float* __restrict__ gamma,
    const float* __restrict__ beta)
{
    const int idx = blockIdx.x * blockDim.x + threadIdx.x;
    const int c = ((idx * 4) >> 12) & (CCH - 1);
    const float inv = 1.f / (float)NSTAT;
    float mean = g_csum[c] * inv;
    float var = g_csum2[c] * inv - mean * mean;
    float s = gamma[c] * rsqrtf(var + 1e-5f);
    float bb = beta[c] - mean * s;
    float4 x = reinterpret_cast<float4*>(out)[idx];
    x.x = x.x * s + bb;
    x.y = x.y * s + bb;
    x.z = x.z * s + bb;
    x.w = x.w * s + bb;
    reinterpret_cast<float4*>(out)[idx] = x;
}

// =====================================================================
extern "C" void kernel_launch(void* const* d_in, const int* in_sizes, int n_in,
                              void* d_out, int out_size)
{
    const float* q     = (const float*)d_in[0];
    const float* k     = (const float*)d_in[1];
    const float* v     = (const float*)d_in[2];
    const float* wq    = (const float*)d_in[3];
    const float* wk    = (const float*)d_in[4];
    const float* wv    = (const float*)d_in[5];
    const float* wfc   = (const float*)d_in[6];
    const float* gamma = (const float*)d_in[7];
    const float* beta  = (const float*)d_in[8];
    float* out = (float*)d_out;

    cudaFuncSetAttribute(proj_tc, cudaFuncAttributeMaxDynamicSharedMemorySize, 96 * 1024);
    cudaFuncSetAttribute(fc_tc,   cudaFuncAttributeMaxDynamicSharedMemorySize, 48 * 1024);

    dim3 g1(MROWS / 128, 3);
    proj_tc<<<g1, 256, 96 * 1024>>>(q, k, v, wq, wk, wv);

    attn_kernel<<<BATCH, 256>>>();

    dim3 g3(HW / 64, MROWS / 128);
    fc_tc<<<g3, 256, 48 * 1024>>>(v, wfc, out);

    const int total4 = BATCH * CCH * HW / 4;
    bn_kernel<<<total4 / 256, 256>>>(out, gamma, beta);
}

// round 16
// speedup vs baseline: 1.3933x; 1.3933x over previous
#include <cuda_runtime.h>
#include <cstdint>

#define HW     4096
#define CCH    256
#define BATCH  32
#define PROJ   50
#define NHEAD  5
#define LDIM   10
#define MROWS  (BATCH * CCH)       // 8192
#define FEAT   (CCH * LDIM)        // 2560
#define NSTAT  (BATCH * HW)

// ---------------- scratch ----------------------------------------------------
__device__ float g_P[3 * MROWS * PROJ];
__device__ float g_A[MROWS * PROJ];
__device__ float g_csum[CCH];
__device__ float g_csum2[CCH];

// pack two fp32 into f16x2 (lo = first k in low half), rne
__device__ __forceinline__ uint32_t pack_f16(float lo, float hi) {
    uint32_t d;
    asm("cvt.rn.f16x2.f32 %0, %1, %2;" : "=r"(d) : "f"(hi), "f"(lo));
    return d;
}

__device__ __forceinline__ void mma_f16(float* d, const uint32_t* a, const uint32_t* b) {
    asm volatile(
        "mma.sync.aligned.m16n8k16.row.col.f32.f16.f16.f32 "
        "{%0,%1,%2,%3}, {%4,%5,%6,%7}, {%8,%9}, {%0,%1,%2,%3};"
        : "+f"(d[0]), "+f"(d[1]), "+f"(d[2]), "+f"(d[3])
        : "r"(a[0]), "r"(a[1]), "r"(a[2]), "r"(a[3]), "r"(b[0]), "r"(b[1]));
}

// =====================================================================
// K1: projection GEMM, fp16 HMMA single-term.
// C[8192,50] = A[8192,4096] @ W[4096,50].  BM=128, BN=64(pad), BK=64.
// smem (dynamic 48KB): As [2][8][128][4] words, Bs [2][8][64][4].
// k = p4*8 + pj*2 (+0/1 inside the f16x2 word). Fragment LDS conflict-free.
// 8 warps: 4 in m x 2 in n. Register prefetch 2 iters ahead (8 LDG.128/thr).
// =====================================================================
__global__ __launch_bounds__(256, 2) void proj_tc(
    const float* __restrict__ q, const float* __restrict__ k,
    const float* __restrict__ v,
    const float* __restrict__ wq, const float* __restrict__ wk,
    const float* __restrict__ wv)
{
    extern __shared__ uint32_t sm[];
    uint32_t* As = sm;             // 8192 words (32 KB)
    uint32_t* Bs = sm + 8192;      // 4096 words (16 KB)

#define AIDX(ST, P4, M, PJ) ((((ST) * 8 + (P4)) * 128 + (M)) * 4 + (PJ))
#define BIDX(ST, P4, N, PJ) ((((ST) * 8 + (P4)) * 64 + (N)) * 4 + (PJ))

    const int t = blockIdx.y;
    const float* A = (t == 0) ? q : (t == 1) ? k : v;
    const float* W = (t == 0) ? wq : (t == 1) ? wk : wv;
    float* C = g_P + (size_t)t * MROWS * PROJ;

    const int tid  = threadIdx.x;
    const int lane = tid & 31;
    const int warp = tid >> 5;
    const int wm   = warp & 3;
    const int wn   = warp >> 2;
    const int g    = lane >> 2;
    const int tt   = lane & 3;
    const int rowBase = blockIdx.x * 128;

    const int ma   = tid >> 1;       // A loader row
    const int half = tid & 1;        // A loader k-half (0..31 / 32..63)
    const int nb   = tid & 63;       // B loader n
    const int wsel = tid >> 6;       // B loader k-16-group

    const float* aPtr = A + (size_t)(rowBase + ma) * HW + half * 32;

    float4 pa[8];
    float  pb[16];
    float  acc[2][4][4];
#pragma unroll
    for (int mt = 0; mt < 2; mt++)
#pragma unroll
        for (int nt = 0; nt < 4; nt++)
#pragma unroll
            for (int r = 0; r < 4; r++) acc[mt][nt][r] = 0.f;

#define LOAD_REGS(K0)                                                         \
    do {                                                                      \
        _Pragma("unroll")                                                     \
        for (int s4 = 0; s4 < 8; s4++)                                        \
            pa[s4] = *(const float4*)&aPtr[(K0) + s4 * 4];                    \
        _Pragma("unroll")                                                     \
        for (int j = 0; j < 16; j++) {                                        \
            int kk = (K0) + wsel * 16 + j;                                    \
            pb[j] = (nb < PROJ) ? W[(size_t)kk * PROJ + nb] : 0.f;            \
        }                                                                     \
    } while (0)

#define STORE_SMEM(ST)                                                        \
    do {                                                                      \
        _Pragma("unroll")                                                     \
        for (int s4 = 0; s4 < 8; s4++) {                                      \
            int p4 = half * 4 + (s4 >> 1);                                    \
            int pj = (s4 & 1) * 2;                                            \
            uint2 u;                                                          \
            u.x = pack_f16(pa[s4].x, pa[s4].y);                               \
            u.y = pack_f16(pa[s4].z, pa[s4].w);                               \
            *(uint2*)&As[AIDX(ST, p4, ma, pj)] = u;                           \
        }                                                                     \
        _Pragma("unroll")                                                     \
        for (int jj = 0; jj < 8; jj++) {                                      \
            int p4 = wsel * 2 + (jj >> 2);                                    \
            int pj = jj & 3;                                                  \
            Bs[BIDX(ST, p4, nb, pj)] = pack_f16(pb[2 * jj], pb[2 * jj + 1]); \
        }                                                                     \
    } while (0)

    // prologue
    LOAD_REGS(0);
    STORE_SMEM(0);
    LOAD_REGS(64);
    __syncthreads();

    const int NIT = HW / 64;
    for (int it = 0; it < NIT; it++) {
        const int st = it & 1;
        if (it + 1 < NIT) STORE_SMEM(st ^ 1);
        if (it + 2 < NIT) LOAD_REGS((it + 2) * 64);

        // compute stage st: four k16 steps
#pragma unroll
        for (int ck = 0; ck < 4; ck++) {
            uint32_t af[2][4], bf[4][2];
#pragma unroll
            for (int mt = 0; mt < 2; mt++) {
                int mo = wm * 32 + mt * 16;
                af[mt][0] = As[AIDX(st, ck * 2, mo + g, tt)];
                af[mt][1] = As[AIDX(st, ck * 2, mo + 8 + g, tt)];
                af[mt][2] = As[AIDX(st, ck * 2 + 1, mo + g, tt)];
                af[mt][3] = As[AIDX(st, ck * 2 + 1, mo + 8 + g, tt)];
            }
#pragma unroll
            for (int nt = 0; nt < 4; nt++) {
                int no = wn * 32 + nt * 8;
                bf[nt][0] = Bs[BIDX(st, ck * 2, no + g, tt)];
                bf[nt][1] = Bs[BIDX(st, ck * 2 + 1, no + g, tt)];
            }
#pragma unroll
            for (int mt = 0; mt < 2; mt++)
#pragma unroll
                for (int nt = 0; nt < 4; nt++)
                    mma_f16(acc[mt][nt], af[mt], bf[nt]);
        }
        __syncthreads();
    }
#undef LOAD_REGS
#undef STORE_SMEM

    // epilogue
#pragma unroll
    for (int mt = 0; mt < 2; mt++) {
        int r0 = rowBase + wm * 32 + mt * 16 + g;
#pragma unroll
        for (int nt = 0; nt < 4; nt++) {
            int c0 = wn * 32 + nt * 8 + tt * 2;
            if (c0 < PROJ) {
                *(float2*)&C[(size_t)r0 * PROJ + c0] =
                    make_float2(acc[mt][nt][0], acc[mt][nt][1]);
                *(float2*)&C[(size_t)(r0 + 8) * PROJ + c0] =
                    make_float2(acc[mt][nt][2], acc[mt][nt][3]);
            }
        }
    }
}

// =====================================================================
// K2: tiny attention per batch. Also zeroes BN accumulators.
// =====================================================================
__global__ __launch_bounds__(256) void attn_kernel()
{
    __shared__ float sS[NHEAD * NHEAD];
    __shared__ float sAttn[NHEAD * NHEAD];

    const int b = blockIdx.x;
    const int c = threadIdx.x;
    const int lane = threadIdx.x & 31;

    if (blockIdx.x == 0) { g_csum[c] = 0.f; g_csum2[c] = 0.f; }
    if (c < NHEAD * NHEAD) sS[c] = 0.f;
    __syncthreads();

    const size_t rowOff = (size_t)(b * CCH + c) * PROJ;
    const float* Pq = g_P + rowOff;
    const float* Pk = g_P + (size_t)MROWS * PROJ + rowOff;
    const float* Pv = g_P + 2 * (size_t)MROWS * PROJ + rowOff;

    float qv[PROJ], kv[PROJ];
#pragma unroll
    for (int x = 0; x < PROJ / 2; x++) {
        float2 a = *(const float2*)&Pq[x * 2];
        float2 bq = *(const float2*)&Pk[x * 2];
        qv[x * 2] = a.x; qv[x * 2 + 1] = a.y;
        kv[x * 2] = bq.x; kv[x * 2 + 1] = bq.y;
    }

#pragma unroll
    for (int i = 0; i < NHEAD; i++) {
#pragma unroll
        for (int j = 0; j < NHEAD; j++) {
            float s = 0.f;
#pragma unroll
            for (int l = 0; l < LDIM; l++) s += qv[i * LDIM + l] * kv[j * LDIM + l];
#pragma unroll
            for (int off = 16; off; off >>= 1)
                s += __shfl_down_sync(0xffffffffu, s, off);
            if (lane == 0) atomicAdd(&sS[i * NHEAD + j], s);
        }
    }
    __syncthreads();

    if (c < NHEAD) {
        const float inv_scale = rsqrtf((float)FEAT);
        float row[NHEAD];
        float mx = -1e30f;
#pragma unroll
        for (int j = 0; j < NHEAD; j++) {
            row[j] = sS[c * NHEAD + j] * inv_scale;
            mx = fmaxf(mx, row[j]);
        }
        float sum = 0.f;
#pragma unroll
        for (int j = 0; j < NHEAD; j++) { row[j] = __expf(row[j] - mx); sum += row[j]; }
        float rinv = 1.f / sum;
#pragma unroll
        for (int j = 0; j < NHEAD; j++) sAttn[c * NHEAD + j] = row[j] * rinv;
    }
    __syncthreads();

    float v50[PROJ];
#pragma unroll
    for (int x = 0; x < PROJ / 2; x++) {
        float2 a = *(const float2*)&Pv[x * 2];
        v50[x * 2] = a.x; v50[x * 2 + 1] = a.y;
    }

    float* Aout = g_A + rowOff;
#pragma unroll
    for (int i = 0; i < NHEAD; i++) {
#pragma unroll
        for (int l = 0; l < LDIM; l += 2) {
            float a0 = v50[i * LDIM + l], a1 = v50[i * LDIM + l + 1];
#pragma unroll
            for (int j = 0; j < NHEAD; j++) {
                float w = sAttn[i * NHEAD + j];
                a0 += w * v50[j * LDIM + l];
                a1 += w * v50[j * LDIM + l + 1];
            }
            *(float2*)&Aout[i * LDIM + l] = make_float2(a0, a1);
        }
    }
}

// =====================================================================
// K3: FC GEMM (fp16 HMMA) + residual + BN partial stats.
// out[m,n] = vf[m,n] + A[m,:50] @ Wfc[:50,n].  BM=128, BN=64, K pad 64.
// =====================================================================
__global__ __launch_bounds__(256) void fc_tc(
    const float* __restrict__ vf, const float* __restrict__ wfc,
    float* __restrict__ out)
{
    __shared__ uint32_t As[8][128][4];   // 16 KB, k = p4*8 + pj*2
    __shared__ uint32_t Bs[8][64][4];    //  8 KB

    const int tid  = threadIdx.x;
    const int lane = tid & 31;
    const int warp = tid >> 5;
    const int wm   = warp & 3;
    const int wn   = warp >> 2;
    const int g    = lane >> 2;
    const int tt   = lane & 3;
    const int rowBase = blockIdx.y * 128;
    const int colBase = blockIdx.x * 64;

    // A tile: 8*128*4 = 4096 words
#pragma unroll
    for (int ii = 0; ii < 16; ii++) {
        int widx = ii * 256 + tid;
        int p4 = widx >> 9;
        int m  = (widx >> 2) & 127;
        int pj = widx & 3;
        int kk = p4 * 8 + pj * 2;
        const float* src = &g_A[(size_t)(rowBase + m) * PROJ + kk];
        float v0 = (kk < PROJ) ? src[0] : 0.f;
        float v1 = (kk + 1 < PROJ) ? src[1] : 0.f;
        As[p4][m][pj] = pack_f16(v0, v1);
    }
    // B tile: 8*64*4 = 2048 words
#pragma unroll
    for (int ii = 0; ii < 8; ii++) {
        int widx = ii * 256 + tid;
        int p4 = widx >> 8;
        int n  = (widx >> 2) & 63;
        int pj = widx & 3;
        int kk = p4 * 8 + pj * 2;
        float v0 = (kk < PROJ) ? wfc[(size_t)kk * HW + colBase + n] : 0.f;
        float v1 = (kk + 1 < PROJ) ? wfc[(size_t)(kk + 1) * HW + colBase + n] : 0.f;
        Bs[p4][n][pj] = pack_f16(v0, v1);
    }
    __syncthreads();

    float acc[2][4][4];
#pragma unroll
    for (int mt = 0; mt < 2; mt++)
#pragma unroll
        for (int nt = 0; nt < 4; nt++)
#pragma unroll
            for (int r = 0; r < 4; r++) acc[mt][nt][r] = 0.f;

#pragma unroll
    for (int ck = 0; ck < 4; ck++) {
        uint32_t af[2][4], bf[4][2];
#pragma unroll
        for (int mt = 0; mt < 2; mt++) {
            int mo = wm * 32 + mt * 16;
            af[mt][0] = As[ck * 2][mo + g][tt];
            af[mt][1] = As[ck * 2][mo + 8 + g][tt];
            af[mt][2] = As[ck * 2 + 1][mo + g][tt];
            af[mt][3] = As[ck * 2 + 1][mo + 8 + g][tt];
        }
#pragma unroll
        for (int nt = 0; nt < 4; nt++) {
            int no = wn * 32 + nt * 8;
            bf[nt][0] = Bs[ck * 2][no + g][tt];
            bf[nt][1] = Bs[ck * 2 + 1][no + g][tt];
        }
#pragma unroll
        for (int mt = 0; mt < 2; mt++)
#pragma unroll
            for (int nt = 0; nt < 4; nt++)
                mma_f16(acc[mt][nt], af[mt], bf[nt]);
    }

#pragma unroll
    for (int mt = 0; mt < 2; mt++) {
        int r0 = rowBase + wm * 32 + mt * 16 + g;
        int r1 = r0 + 8;
        float s0 = 0.f, q0 = 0.f, s1 = 0.f, q1 = 0.f;
#pragma unroll
        for (int nt = 0; nt < 4; nt++) {
            int c0 = colBase + wn * 32 + nt * 8 + tt * 2;
            size_t i00 = (size_t)r0 * HW + c0;
            size_t i10 = (size_t)r1 * HW + c0;
            float2 rv0 = *(const float2*)&vf[i00];
            float2 rv1 = *(const float2*)&vf[i10];
            float v00 = acc[mt][nt][0] + rv0.x;
            float v01 = acc[mt][nt][1] + rv0.y;
            float v10 = acc[mt][nt][2] + rv1.x;
            float v11 = acc[mt][nt][3] + rv1.y;
            *(float2*)&out[i00] = make_float2(v00, v01);
            *(float2*)&out[i10] = make_float2(v10, v11);
            s0 += v00 + v01; q0 += v00 * v00 + v01 * v01;
            s1 += v10 + v11; q1 += v10 * v10 + v11 * v11;
        }
#pragma unroll
        for (int off = 1; off < 4; off <<= 1) {
            s0 += __shfl_xor_sync(0xffffffffu, s0, off);
            q0 += __shfl_xor_sync(0xffffffffu, q0, off);
            s1 += __shfl_xor_sync(0xffffffffu, s1, off);
            q1 += __shfl_xor_sync(0xffffffffu, q1, off);
        }
        if (tt == 0) {
            atomicAdd(&g_csum[r0 & (CCH - 1)],  s0);
            atomicAdd(&g_csum2[r0 & (CCH - 1)], q0);
            atomicAdd(&g_csum[r1 & (CCH - 1)],  s1);
            atomicAdd(&g_csum2[r1 & (CCH - 1)], q1);
        }
    }
}

// =====================================================================
// K4: BatchNorm finalize, in-place. float4 per thread.
// =====================================================================
__global__ __launch_bounds__(256) void bn_kernel(
    float* __restrict__ out, const float* __restrict__ gamma,
    const float* __restrict__ beta)
{
    const int idx = blockIdx.x * blockDim.x + threadIdx.x;
    const int c = ((idx * 4) >> 12) & (CCH - 1);
    const float inv = 1.f / (float)NSTAT;
    float mean = g_csum[c] * inv;
    float var = g_csum2[c] * inv - mean * mean;
    float s = gamma[c] * rsqrtf(var + 1e-5f);
    float bb = beta[c] - mean * s;
    float4 x = reinterpret_cast<float4*>(out)[idx];
    x.x = x.x * s + bb;
    x.y = x.y * s + bb;
    x.z = x.z * s + bb;
    x.w = x.w * s + bb;
    reinterpret_cast<float4*>(out)[idx] = x;
}

// =====================================================================
extern "C" void kernel_launch(void* const* d_in, const int* in_sizes, int n_in,
                              void* d_out, int out_size)
{
    const float* q     = (const float*)d_in[0];
    const float* k     = (const float*)d_in[1];
    const float* v     = (const float*)d_in[2];
    const float* wq    = (const float*)d_in[3];
    const float* wk    = (const float*)d_in[4];
    const float* wv    = (const float*)d_in[5];
    const float* wfc   = (const float*)d_in[6];
    const float* gamma = (const float*)d_in[7];
    const float* beta  = (const float*)d_in[8];
    float* out = (float*)d_out;

    cudaFuncSetAttribute(proj_tc, cudaFuncAttributeMaxDynamicSharedMemorySize, 64 * 1024);

    dim3 g1(MROWS / 128, 3);
    proj_tc<<<g1, 256, 48 * 1024>>>(q, k, v, wq, wk, wv);

    attn_kernel<<<BATCH, 256>>>();

    dim3 g3(HW / 64, MROWS / 128);
    fc_tc<<<g3, 256>>>(v, wfc, out);

    const int total4 = BATCH * CCH * HW / 4;
    bn_kernel<<<total4 / 256, 256>>>(out, gamma, beta);
}